// round 1
// baseline (speedup 1.0000x reference)
#include <cuda_runtime.h>

// ---------------------------------------------------------------------------
// HiPPO-LegT via chunked convolution + one big GEMM.
//
//  out[l, r, n] = sum_{k<=l} (A^{l-k} B)[n] * f[r, k]     (r = b*64+m, R=512)
//
//  Chunk T=128, C=8.  v_j = A^j B.
//  For l = i*T + t:
//    out = sum_{k=0}^{t} v_{t-k}[n] f[r, iT+k]  +  (A^{t+1} h_{i-1})[n]
//  where h_{i-1} = out[i*T - 1, r, :]  (h_{-1} = 0).
//
//  One GEMM:  Out(4096 x 32768) = X(4096 x 384) @ Kmat(384 x 32768)
//    X row (i,r)   = [ f[r, iT .. iT+127]  |  h_{i-1}[r, 0..255] ]
//    Kmat col (t,n): rows k<128:  (k<=t) ? v_{t-k}[n] : 0
//                    rows 128+m:  A^{t+1}[n, m]
// ---------------------------------------------------------------------------

#define L_LEN 1024
#define R_DIM 512
#define N_ST  256
#define T_CH  128
#define C_CH  8
#define KTOT  384            // T_CH + N_ST
#define NCOL  32768          // T_CH * N_ST
#define MROWS 4096           // C_CH * R_DIM
#define MAT   65536          // 256*256

// ---- device scratch (no allocation allowed) ----
__device__ float g_Apow[129 * MAT];          // A^1 .. A^128 at indices 1..128
__device__ float g_V[T_CH * N_ST];           // v_j = A^j B, j=0..127
__device__ float g_Qt[MAT];                  // (A^128)^T
__device__ float g_Kmat[(size_t)KTOT * NCOL];
__device__ float g_X[(size_t)MROWS * KTOT];
__device__ float g_S[C_CH * R_DIM * N_ST];   // chunk-local end states
__device__ float g_H[C_CH * R_DIM * N_ST];   // carried states h_i

// ---------------------------------------------------------------------------
__global__ void init_a_kernel(const float* __restrict__ A) {
    int idx = blockIdx.x * blockDim.x + threadIdx.x;
    if (idx < MAT) g_Apow[MAT + idx] = A[idx];
}

__global__ void init_x_kernel(const float* __restrict__ inp) {
    int idx = blockIdx.x * blockDim.x + threadIdx.x;
    if (idx >= MROWS * KTOT) return;
    int row = idx / KTOT;
    int k   = idx - row * KTOT;
    int i = row >> 9;        // chunk
    int r = row & 511;
    float v = 0.f;
    if (k < T_CH) v = inp[r * 1024 + i * T_CH + k];
    g_X[idx] = v;            // h-part zeroed; chunks >=1 filled later
}

// ---- 64x64-tile fp32 GEMM body (row-major, ldim=256, K=256) ----
__device__ __forceinline__ void gemm64_body(const float* __restrict__ Am,
                                            const float* __restrict__ Bm,
                                            float* __restrict__ Cm,
                                            const float* __restrict__ bias) {
    __shared__ float As[16][64];
    __shared__ float Bs[16][64];
    const int brow = blockIdx.y * 64;
    const int bcol = blockIdx.x * 64;
    const int tid = threadIdx.x;
    const int tr = tid >> 4, tc = tid & 15;
    const int alr = tid >> 2, alc = (tid & 3) * 4;
    const int blr = tid >> 4, blc = (tid & 15) * 4;
    float acc[4][4] = {};
    for (int k0 = 0; k0 < 256; k0 += 16) {
        float4 a4 = *(const float4*)&Am[(brow + alr) * 256 + k0 + alc];
        As[alc + 0][alr] = a4.x; As[alc + 1][alr] = a4.y;
        As[alc + 2][alr] = a4.z; As[alc + 3][alr] = a4.w;
        float4 b4 = *(const float4*)&Bm[(k0 + blr) * 256 + bcol + blc];
        *(float4*)&Bs[blr][blc] = b4;
        __syncthreads();
#pragma unroll
        for (int k = 0; k < 16; k++) {
            float av[4], bv[4];
            *(float4*)&av[0] = *(const float4*)&As[k][tr * 4];
            *(float4*)&bv[0] = *(const float4*)&Bs[k][tc * 4];
#pragma unroll
            for (int ii = 0; ii < 4; ii++)
#pragma unroll
                for (int jj = 0; jj < 4; jj++)
                    acc[ii][jj] += av[ii] * bv[jj];
        }
        __syncthreads();
    }
#pragma unroll
    for (int ii = 0; ii < 4; ii++) {
        int rr = brow + tr * 4 + ii;
        int cc = bcol + tc * 4;
        float4 v;
        v.x = acc[ii][0]; v.y = acc[ii][1]; v.z = acc[ii][2]; v.w = acc[ii][3];
        if (bias) {
            float4 b = *(const float4*)&bias[rr * 256 + cc];
            v.x += b.x; v.y += b.y; v.z += b.z; v.w += b.w;
        }
        *(float4*)&Cm[rr * 256 + cc] = v;
    }
}

// A^{d+j} = A^d @ A^j  for j = 1..d   (grid (4,4,d))
__global__ void pow_double_kernel(int d) {
    int j = blockIdx.z + 1;
    gemm64_body(g_Apow + (size_t)d * MAT,
                g_Apow + (size_t)j * MAT,
                g_Apow + (size_t)(d + j) * MAT, nullptr);
}

// H[i+1] = H[i] @ Qt + S[i+1]   (grid (4,8))
__global__ void combine_kernel(int i) {
    gemm64_body(g_H + (size_t)i * (R_DIM * N_ST), g_Qt,
                g_H + (size_t)(i + 1) * (R_DIM * N_ST),
                g_S + (size_t)(i + 1) * (R_DIM * N_ST));
}

// v_j = A^j B  (grid 128 blocks of 256)
__global__ void v_kernel(const float* __restrict__ Bv) {
    __shared__ float bs[256];
    int j = blockIdx.x, n = threadIdx.x;
    bs[n] = Bv[n];
    __syncthreads();
    if (j == 0) { g_V[n] = bs[n]; return; }
    const float* Am = g_Apow + (size_t)j * MAT;
    float s = 0.f;
#pragma unroll 8
    for (int m = 0; m < 256; m++) s += Am[n * 256 + m] * bs[m];
    g_V[j * 256 + n] = s;
}

__global__ void qt_kernel() {
    int idx = blockIdx.x * blockDim.x + threadIdx.x;
    if (idx >= MAT) return;
    int m = idx >> 8, n = idx & 255;
    g_Qt[m * 256 + n] = g_Apow[(size_t)128 * MAT + n * 256 + m];
}

// Kmat W-part: rows k = 0..127
__global__ void kmat_w_kernel() {
    int idx = blockIdx.x * blockDim.x + threadIdx.x;
    if (idx >= T_CH * NCOL) return;
    int k = idx / NCOL;
    int rem = idx - k * NCOL;
    int t = rem >> 8, n = rem & 255;
    g_Kmat[idx] = (k <= t) ? g_V[(t - k) * 256 + n] : 0.f;
}

// Kmat G-part: row 128+m, col (t,n) = A^{t+1}[n,m]  (transpose via smem tile)
__global__ void kmat_g_kernel() {
    __shared__ float sm[32][33];
    int t = blockIdx.z;
    int mb = blockIdx.x * 32, nb = blockIdx.y * 32;
    const float* Am = g_Apow + (size_t)(t + 1) * MAT;
    int tx = threadIdx.x, ty = threadIdx.y;
#pragma unroll
    for (int yy = 0; yy < 32; yy += 8)
        sm[ty + yy][tx] = Am[(nb + ty + yy) * 256 + mb + tx];   // sm[n_l][m_l]
    __syncthreads();
#pragma unroll
    for (int yy = 0; yy < 32; yy += 8) {
        int m = mb + ty + yy;
        g_Kmat[(size_t)(128 + m) * NCOL + t * 256 + nb + tx] = sm[tx][ty + yy];
    }
}

// chunk-local end states: s_i[r,n] = sum_k v_{127-k}[n] f[r, iT+k]
__global__ void s_kernel(const float* __restrict__ inp) {
    __shared__ float fs[128];
    int r = blockIdx.x, i = blockIdx.y, n = threadIdx.x;
    if (n < 128) fs[n] = inp[r * 1024 + i * T_CH + n];
    __syncthreads();
    float s = 0.f;
#pragma unroll 4
    for (int k = 0; k < 128; k++)
        s += g_V[(127 - k) * 256 + n] * fs[k];
    g_S[(i * 512 + r) * 256 + n] = s;
    if (i == 0) g_H[r * 256 + n] = s;   // h_0 = s_0
}

// scatter H[i] -> X rows of chunk i+1, cols 128..383
__global__ void xh_kernel() {
    int idx = blockIdx.x * blockDim.x + threadIdx.x;
    if (idx >= 7 * R_DIM * N_ST) return;
    int i = idx / (R_DIM * N_ST);
    int rem = idx - i * (R_DIM * N_ST);
    int r = rem >> 8, m = rem & 255;
    g_X[(size_t)((i + 1) * 512 + r) * KTOT + 128 + m] = g_H[idx];
}

// ---------------------------------------------------------------------------
// Main GEMM: Out(4096 x 32768) = X(4096x384) @ Kmat(384x32768), fp32,
// 128x128 tile, 256 threads, 8x8 micro, double-buffered smem. Epilogue
// scatters to out[(i*128+t)*131072 + r*256 + n].
// ---------------------------------------------------------------------------
__global__ __launch_bounds__(256, 2) void main_gemm_kernel(float* __restrict__ out) {
    __shared__ float Xs[2][16][128];
    __shared__ float Ks[2][16][128];
    const int tid = threadIdx.x;
    const int bn = blockIdx.x;      // 0..255 (col tiles)
    const int bm = blockIdx.y;      // 0..31  (row tiles)
    const int row0 = bm * 128;
    const int col0 = bn * 128;

    const int tr = tid >> 4;        // 0..15
    const int tc = tid & 15;

    const int xlr = tid >> 2;               // 0..63
    const int xlc = (tid & 3) * 4;          // 0,4,8,12
    const int klr = tid >> 5;               // 0..7
    const int klc = (tid & 31) * 4;         // 0..124

    const float* Xp = g_X + (size_t)row0 * KTOT;
    const float* Kp = g_Kmat + col0;

    float acc[8][8] = {};

    // preload tile 0
    {
        float4 a0 = *(const float4*)&Xp[(size_t)xlr * KTOT + xlc];
        float4 a1 = *(const float4*)&Xp[(size_t)(xlr + 64) * KTOT + xlc];
        Xs[0][xlc + 0][xlr] = a0.x; Xs[0][xlc + 1][xlr] = a0.y;
        Xs[0][xlc + 2][xlr] = a0.z; Xs[0][xlc + 3][xlr] = a0.w;
        Xs[0][xlc + 0][xlr + 64] = a1.x; Xs[0][xlc + 1][xlr + 64] = a1.y;
        Xs[0][xlc + 2][xlr + 64] = a1.z; Xs[0][xlc + 3][xlr + 64] = a1.w;
        float4 b0 = *(const float4*)&Kp[(size_t)klr * NCOL + klc];
        float4 b1 = *(const float4*)&Kp[(size_t)(klr + 8) * NCOL + klc];
        *(float4*)&Ks[0][klr][klc] = b0;
        *(float4*)&Ks[0][klr + 8][klc] = b1;
    }
    __syncthreads();

    for (int kt = 0; kt < 24; kt++) {
        const int cur = kt & 1;
        float4 a0, a1, b0, b1;
        if (kt < 23) {
            const int kb = (kt + 1) * 16;
            a0 = *(const float4*)&Xp[(size_t)xlr * KTOT + kb + xlc];
            a1 = *(const float4*)&Xp[(size_t)(xlr + 64) * KTOT + kb + xlc];
            b0 = *(const float4*)&Kp[(size_t)(kb + klr) * NCOL + klc];
            b1 = *(const float4*)&Kp[(size_t)(kb + klr + 8) * NCOL + klc];
        }
#pragma unroll
        for (int k = 0; k < 16; k++) {
            float av[8], bv[8];
            *(float4*)&av[0] = *(const float4*)&Xs[cur][k][tr * 8];
            *(float4*)&av[4] = *(const float4*)&Xs[cur][k][tr * 8 + 4];
            *(float4*)&bv[0] = *(const float4*)&Ks[cur][k][tc * 8];
            *(float4*)&bv[4] = *(const float4*)&Ks[cur][k][tc * 8 + 4];
#pragma unroll
            for (int ii = 0; ii < 8; ii++)
#pragma unroll
                for (int jj = 0; jj < 8; jj++)
                    acc[ii][jj] += av[ii] * bv[jj];
        }
        if (kt < 23) {
            const int nxt = cur ^ 1;
            Xs[nxt][xlc + 0][xlr] = a0.x; Xs[nxt][xlc + 1][xlr] = a0.y;
            Xs[nxt][xlc + 2][xlr] = a0.z; Xs[nxt][xlc + 3][xlr] = a0.w;
            Xs[nxt][xlc + 0][xlr + 64] = a1.x; Xs[nxt][xlc + 1][xlr + 64] = a1.y;
            Xs[nxt][xlc + 2][xlr + 64] = a1.z; Xs[nxt][xlc + 3][xlr + 64] = a1.w;
            *(float4*)&Ks[nxt][klr][klc] = b0;
            *(float4*)&Ks[nxt][klr + 8][klc] = b1;
        }
        __syncthreads();
    }

    // epilogue: row = i*512 + r, col = t*256 + n  ->  out[(i*128+t)*131072 + r*256 + n]
    const int ich = bm >> 2;
    const int r0  = (row0 & 511) + tr * 8;
    const int t   = bn >> 1;
    const int n0  = (col0 & 255) + tc * 8;
    float* obase = out + (size_t)(ich * 128 + t) * 131072 + n0;
#pragma unroll
    for (int ii = 0; ii < 8; ii++) {
        float* orow = obase + (size_t)(r0 + ii) * 256;
        *(float4*)&orow[0] = *(float4*)&acc[ii][0];
        *(float4*)&orow[4] = *(float4*)&acc[ii][4];
    }
}

// ---------------------------------------------------------------------------
extern "C" void kernel_launch(void* const* d_in, const int* in_sizes, int n_in,
                              void* d_out, int out_size) {
    const float* inp = (const float*)d_in[0];   // (8,64,1024)
    const float* A   = (const float*)d_in[1];   // (256,256)
    const float* Bv  = (const float*)d_in[2];   // (256,)
    float* out = (float*)d_out;

    init_a_kernel<<<256, 256>>>(A);
    init_x_kernel<<<(MROWS * KTOT + 255) / 256, 256>>>(inp);

    // A^1 .. A^128 via log doubling (7 levels)
    for (int d = 1; d <= 64; d <<= 1)
        pow_double_kernel<<<dim3(4, 4, d), 256>>>(d);

    v_kernel<<<128, 256>>>(Bv);
    qt_kernel<<<256, 256>>>();
    kmat_w_kernel<<<(T_CH * NCOL + 255) / 256, 256>>>();
    kmat_g_kernel<<<dim3(8, 8, 128), dim3(32, 8)>>>();
    s_kernel<<<dim3(512, 8), 256>>>(inp);

    for (int i = 0; i < 6; i++)                 // h_1 .. h_6
        combine_kernel<<<dim3(4, 8), 256>>>(i);
    xh_kernel<<<(7 * R_DIM * N_ST + 255) / 256, 256>>>();

    main_gemm_kernel<<<dim3(256, 32), 256>>>(out);
}

// round 3
// speedup vs baseline: 2.0125x; 2.0125x over previous
#include <cuda_runtime.h>
#include <cuda_bf16.h>
#include <cstdint>

// ---------------------------------------------------------------------------
// HiPPO-LegT: chunked convolution + one big GEMM.
// Main GEMM on mma.sync bf16 (3-limb split: AhBh + AhBl + AlBh, fp32 acc).
//
//  out[l, r, n] = sum_{k<=l} (A^{l-k} B)[n] * f[r, k]   (r = b*64+m, R=512)
//  Chunk T=128, C=8, v_j = A^j B:
//    out(i*T+t) = sum_{k<=t} v_{t-k} f[r,iT+k] + A^{t+1} h_{i-1}
//  One GEMM: Out(4096 x 32768) = X(4096 x 384) @ Kmat(384 x 32768)
// ---------------------------------------------------------------------------

#define N_ST   256
#define T_CH   128
#define MAT    65536
#define NCHUNK 6
#define AB_BLK 16384              // bytes: 128 rows x 64 k bf16 (swizzled)
#define BB_BLK 32768              // bytes: 256 rows x 64 k bf16 (swizzled)

// main mma kernel smem: per stage [Ah 16K][Al 16K][Bh 16K][Bl 16K]
#define ST_AL  16384
#define ST_BH  32768
#define ST_BL  49152
#define ST_SZ  65536
#define SMEM_SZ (2 * ST_SZ)

// ---- device scratch ----
__device__ float g_Apow[129 * MAT];                    // A^1..A^128 at 1..128
__device__ float g_V[T_CH * N_ST];                     // v_j = A^j B
__device__ float g_Qt[MAT];                            // (A^128)^T
__device__ float g_S[8 * 512 * N_ST];
__device__ float g_H[8 * 512 * N_ST];
__device__ __nv_bfloat16 g_Ah[(size_t)32 * NCHUNK * 8192];
__device__ __nv_bfloat16 g_Al[(size_t)32 * NCHUNK * 8192];
__device__ __nv_bfloat16 g_Bh[(size_t)128 * NCHUNK * 16384];
__device__ __nv_bfloat16 g_Bl[(size_t)128 * NCHUNK * 16384];

// ---------------------------------------------------------------------------
__device__ __forceinline__ uint32_t smem_u32(const void* p) {
    uint32_t a;
    asm("{ .reg .u64 t; cvta.to.shared.u64 t, %1; cvt.u32.u64 %0, t; }" : "=r"(a) : "l"(p));
    return a;
}
__device__ __forceinline__ void cp16(uint32_t s, const void* g) {
    asm volatile("cp.async.cg.shared.global [%0], [%1], 16;" :: "r"(s), "l"(g));
}
#define CP_COMMIT() asm volatile("cp.async.commit_group;" ::: "memory")
#define CP_WAIT(n)  asm volatile("cp.async.wait_group %0;" :: "n"(n) : "memory")

__device__ __forceinline__ void ldm4(uint32_t* r, uint32_t addr) {
    asm volatile("ldmatrix.sync.aligned.m8n8.x4.shared.b16 {%0,%1,%2,%3}, [%4];"
                 : "=r"(r[0]), "=r"(r[1]), "=r"(r[2]), "=r"(r[3]) : "r"(addr));
}
__device__ __forceinline__ void mma16816(float* d, const uint32_t* a,
                                         uint32_t b0, uint32_t b1) {
    asm volatile(
        "mma.sync.aligned.m16n8k16.row.col.f32.bf16.bf16.f32 "
        "{%0,%1,%2,%3}, {%4,%5,%6,%7}, {%8,%9}, {%0,%1,%2,%3};"
        : "+f"(d[0]), "+f"(d[1]), "+f"(d[2]), "+f"(d[3])
        : "r"(a[0]), "r"(a[1]), "r"(a[2]), "r"(a[3]), "r"(b0), "r"(b1));
}

__device__ __forceinline__ uint32_t swz(uint32_t off) { return off ^ ((off >> 3) & 0x70); }

__device__ __forceinline__ unsigned short bfbits(float x) {
    __nv_bfloat16 b = __float2bfloat16(x);
    return *reinterpret_cast<unsigned short*>(&b);
}
__device__ __forceinline__ void split2(float x, unsigned short& h, unsigned short& l) {
    __nv_bfloat16 bh = __float2bfloat16(x);
    h = *reinterpret_cast<unsigned short*>(&bh);
    l = bfbits(x - __bfloat162float(bh));
}

// ---------------------------------------------------------------------------
// prologue kernels (fp32 SIMT, proven in round 1)
// ---------------------------------------------------------------------------
__global__ void init_a_kernel(const float* __restrict__ A) {
    int idx = blockIdx.x * blockDim.x + threadIdx.x;
    if (idx < MAT) g_Apow[MAT + idx] = A[idx];
}

__device__ __forceinline__ void gemm64_body(const float* __restrict__ Am,
                                            const float* __restrict__ Bm,
                                            float* __restrict__ Cm,
                                            const float* __restrict__ bias) {
    __shared__ float As[16][64];
    __shared__ float Bs[16][64];
    const int brow = blockIdx.y * 64;
    const int bcol = blockIdx.x * 64;
    const int tid = threadIdx.x;
    const int tr = tid >> 4, tc = tid & 15;
    const int alr = tid >> 2, alc = (tid & 3) * 4;
    const int blr = tid >> 4, blc = (tid & 15) * 4;
    float acc[4][4] = {};
    for (int k0 = 0; k0 < 256; k0 += 16) {
        float4 a4 = *(const float4*)&Am[(brow + alr) * 256 + k0 + alc];
        As[alc + 0][alr] = a4.x; As[alc + 1][alr] = a4.y;
        As[alc + 2][alr] = a4.z; As[alc + 3][alr] = a4.w;
        float4 b4 = *(const float4*)&Bm[(k0 + blr) * 256 + bcol + blc];
        *(float4*)&Bs[blr][blc] = b4;
        __syncthreads();
#pragma unroll
        for (int k = 0; k < 16; k++) {
            float av[4], bv[4];
            *(float4*)&av[0] = *(const float4*)&As[k][tr * 4];
            *(float4*)&bv[0] = *(const float4*)&Bs[k][tc * 4];
#pragma unroll
            for (int ii = 0; ii < 4; ii++)
#pragma unroll
                for (int jj = 0; jj < 4; jj++)
                    acc[ii][jj] += av[ii] * bv[jj];
        }
        __syncthreads();
    }
#pragma unroll
    for (int ii = 0; ii < 4; ii++) {
        int rr = brow + tr * 4 + ii;
        int cc = bcol + tc * 4;
        float4 v;
        v.x = acc[ii][0]; v.y = acc[ii][1]; v.z = acc[ii][2]; v.w = acc[ii][3];
        if (bias) {
            float4 b = *(const float4*)&bias[rr * 256 + cc];
            v.x += b.x; v.y += b.y; v.z += b.z; v.w += b.w;
        }
        *(float4*)&Cm[rr * 256 + cc] = v;
    }
}

__global__ void pow_double_kernel(int d) {
    int j = blockIdx.z + 1;
    gemm64_body(g_Apow + (size_t)d * MAT, g_Apow + (size_t)j * MAT,
                g_Apow + (size_t)(d + j) * MAT, nullptr);
}

__global__ void combine_kernel(int i) {
    gemm64_body(g_H + (size_t)i * (512 * N_ST), g_Qt,
                g_H + (size_t)(i + 1) * (512 * N_ST),
                g_S + (size_t)(i + 1) * (512 * N_ST));
}

__global__ void v_kernel(const float* __restrict__ Bv) {
    __shared__ float bs[256];
    int j = blockIdx.x, n = threadIdx.x;
    bs[n] = Bv[n];
    __syncthreads();
    if (j == 0) { g_V[n] = bs[n]; return; }
    const float* Am = g_Apow + (size_t)j * MAT;
    float s = 0.f;
#pragma unroll 8
    for (int m = 0; m < 256; m++) s += Am[n * 256 + m] * bs[m];
    g_V[j * 256 + n] = s;
}

__global__ void qt_kernel() {
    int idx = blockIdx.x * blockDim.x + threadIdx.x;
    if (idx >= MAT) return;
    int m = idx >> 8, n = idx & 255;
    g_Qt[m * 256 + n] = g_Apow[(size_t)128 * MAT + n * 256 + m];
}

__global__ void s_kernel(const float* __restrict__ inp) {
    __shared__ float fs[128];
    int r = blockIdx.x, i = blockIdx.y, n = threadIdx.x;
    if (n < 128) fs[n] = inp[r * 1024 + i * T_CH + n];
    __syncthreads();
    float s = 0.f;
#pragma unroll 4
    for (int k = 0; k < 128; k++)
        s += g_V[(127 - k) * 256 + n] * fs[k];
    g_S[(i * 512 + r) * 256 + n] = s;
    if (i == 0) g_H[r * 256 + n] = s;
}

// ---------------------------------------------------------------------------
// limb-split packers: write per-(tile,chunk) blocks, SW128-swizzled,
// exactly the smem image the mma kernel wants.
// B block (t, kc): 256 rows(n) x 64 k bf16;   value = Kmat[kc*64+kk][t*256+n]
// A block (rt, kc): 128 rows(m) x 64 k bf16;  value = X[rt*128+row][kc*64+kk]
// ---------------------------------------------------------------------------
__global__ void b_limbs_kernel() {
    const int blk = blockIdx.x;            // t*6 + kc
    const int t = blk / NCHUNK, kc = blk % NCHUNK;
    const int tid = threadIdx.x;
    const int kk0 = (tid & 15) * 4;
    const size_t base = (size_t)blk * BB_BLK;
    char* dh = (char*)g_Bh + base;
    char* dl = (char*)g_Bl + base;
    for (int it = 0; it < 16; it++) {
        int n = it * 16 + (tid >> 4);
        float v[4];
        if (kc < 2) {
            int k0 = kc * 64 + kk0;
#pragma unroll
            for (int q = 0; q < 4; q++) {
                int k = k0 + q;
                v[q] = (k <= t) ? g_V[(t - k) * 256 + n] : 0.f;
            }
        } else {
            int m0 = kc * 64 + kk0 - 128;
            float4 a4 = *(const float4*)&g_Apow[(size_t)(t + 1) * MAT + n * 256 + m0];
            v[0] = a4.x; v[1] = a4.y; v[2] = a4.z; v[3] = a4.w;
        }
        unsigned short h[4], l[4];
#pragma unroll
        for (int q = 0; q < 4; q++) split2(v[q], h[q], l[q]);
        uint2 ph, pl;
        ph.x = (uint32_t)h[0] | ((uint32_t)h[1] << 16);
        ph.y = (uint32_t)h[2] | ((uint32_t)h[3] << 16);
        pl.x = (uint32_t)l[0] | ((uint32_t)l[1] << 16);
        pl.y = (uint32_t)l[2] | ((uint32_t)l[3] << 16);
        uint32_t off = swz((uint32_t)(n * 128 + kk0 * 2));
        *(uint2*)(dh + off) = ph;
        *(uint2*)(dl + off) = pl;
    }
}

__global__ void a_limbs_kernel(const float* __restrict__ inp) {
    const int blk = blockIdx.x;            // rt*6 + kc
    const int rt = blk / NCHUNK, kc = blk % NCHUNK;
    const int i = rt >> 2;
    const int tid = threadIdx.x;
    const int kk0 = (tid & 15) * 4;
    const size_t base = (size_t)blk * AB_BLK;
    char* dh = (char*)g_Ah + base;
    char* dl = (char*)g_Al + base;
    for (int it = 0; it < 8; it++) {
        int row = it * 16 + (tid >> 4);
        int r = (rt & 3) * 128 + row;
        float v[4];
        if (kc < 2) {
            float4 f4 = *(const float4*)&inp[r * 1024 + i * 128 + kc * 64 + kk0];
            v[0] = f4.x; v[1] = f4.y; v[2] = f4.z; v[3] = f4.w;
        } else if (i == 0) {
            v[0] = v[1] = v[2] = v[3] = 0.f;
        } else {
            float4 f4 = *(const float4*)&g_H[(size_t)((i - 1) * 512 + r) * 256 +
                                             (kc - 2) * 64 + kk0];
            v[0] = f4.x; v[1] = f4.y; v[2] = f4.z; v[3] = f4.w;
        }
        unsigned short h[4], l[4];
#pragma unroll
        for (int q = 0; q < 4; q++) split2(v[q], h[q], l[q]);
        uint2 ph, pl;
        ph.x = (uint32_t)h[0] | ((uint32_t)h[1] << 16);
        ph.y = (uint32_t)h[2] | ((uint32_t)h[3] << 16);
        pl.x = (uint32_t)l[0] | ((uint32_t)l[1] << 16);
        pl.y = (uint32_t)l[2] | ((uint32_t)l[3] << 16);
        uint32_t off = swz((uint32_t)(row * 128 + kk0 * 2));
        *(uint2*)(dh + off) = ph;
        *(uint2*)(dl + off) = pl;
    }
}

// ---------------------------------------------------------------------------
// Main GEMM: mma.sync bf16, 3-limb. CTA = 128x128 out tile, K=384 in 6
// chunks of 64, cp.async double-buffered. 8 warps, warp tile 32x64.
// grid (256 col tiles, 32 row tiles).
// ---------------------------------------------------------------------------
__global__ __launch_bounds__(256, 1) void main_mma_kernel(float* __restrict__ out) {
    extern __shared__ char smem[];
    const uint32_t sb = smem_u32(smem);
    const int tid = threadIdx.x;
    const int wid = tid >> 5;
    const int lane = tid & 31;
    const int bx = blockIdx.x;          // 0..255: t = bx>>1, n-half = bx&1
    const int by = blockIdx.y;          // 0..31 row tile

    const int wm = wid & 3;             // warp row: m0 = wm*32
    const int wn = wid >> 1 & 0 ? 0 : (wid >> 2);  // 0..1
    const int m0w = wm * 32;
    const int n0w = (wid >> 2) * 64;

    // global source bases
    const char* Asrc_h = (const char*)g_Ah + (size_t)by * NCHUNK * AB_BLK;
    const char* Asrc_l = (const char*)g_Al + (size_t)by * NCHUNK * AB_BLK;
    const char* Bsrc_h = (const char*)g_Bh + (size_t)(bx >> 1) * NCHUNK * BB_BLK
                         + (size_t)(bx & 1) * 16384;
    const char* Bsrc_l = (const char*)g_Bl + (size_t)(bx >> 1) * NCHUNK * BB_BLK
                         + (size_t)(bx & 1) * 16384;

    // cp.async mapping: each thread copies 4 x 16B per 16KB part
    const uint32_t cpo = (uint32_t)tid * 16;

    // precompute ldmatrix swizzled offsets (stage-base relative)
    // A: tiles mt=0,1 at rows m0w+mt*16 ; lane -> row (lane&15), khalf (lane>>4)
    uint32_t aoff[2][4];
    uint32_t boff[4][4];
    {
        const uint32_t arow = (uint32_t)(m0w + (lane & 15)) * 128;
        const uint32_t khalf = (uint32_t)(lane >> 4) * 16;
#pragma unroll
        for (int mt = 0; mt < 2; mt++)
#pragma unroll
            for (int ks = 0; ks < 4; ks++)
                aoff[mt][ks] = swz(arow + (uint32_t)mt * 16 * 128 + khalf + ks * 32);
        const uint32_t brow = (uint32_t)(n0w + (lane & 15)) * 128;
#pragma unroll
        for (int ng = 0; ng < 4; ng++)
#pragma unroll
            for (int ks = 0; ks < 4; ks++)
                boff[ng][ks] = swz(brow + (uint32_t)ng * 16 * 128 + khalf + ks * 32);
    }

    float acc[2][8][4];
#pragma unroll
    for (int mt = 0; mt < 2; mt++)
#pragma unroll
        for (int nt = 0; nt < 8; nt++)
#pragma unroll
            for (int q = 0; q < 4; q++) acc[mt][nt][q] = 0.f;

    // ---- load stage helper (macro to keep addresses simple) ----
#define LOAD_STAGE(kc, st)                                                      \
    do {                                                                        \
        uint32_t s0 = sb + (st) * ST_SZ + cpo;                                  \
        const char* ga = Asrc_h + (size_t)(kc) * AB_BLK + cpo;                  \
        const char* gb = Asrc_l + (size_t)(kc) * AB_BLK + cpo;                  \
        const char* gc = Bsrc_h + (size_t)(kc) * BB_BLK + cpo;                  \
        const char* gd = Bsrc_l + (size_t)(kc) * BB_BLK + cpo;                  \
        _Pragma("unroll")                                                       \
        for (int q = 0; q < 4; q++) {                                           \
            cp16(s0 + q * 4096,         ga + q * 4096);                         \
            cp16(s0 + ST_AL + q * 4096, gb + q * 4096);                         \
            cp16(s0 + ST_BH + q * 4096, gc + q * 4096);                         \
            cp16(s0 + ST_BL + q * 4096, gd + q * 4096);                         \
        }                                                                       \
        CP_COMMIT();                                                            \
    } while (0)

    LOAD_STAGE(0, 0);
    LOAD_STAGE(1, 1);

    for (int kc = 0; kc < NCHUNK; kc++) {
        if (kc + 2 < NCHUNK) CP_WAIT(1); else CP_WAIT(0);
        __syncthreads();
        const uint32_t st = sb + (uint32_t)(kc & 1) * ST_SZ;
#pragma unroll
        for (int ks = 0; ks < 4; ks++) {
            uint32_t ah[2][4], al[2][4];
#pragma unroll
            for (int mt = 0; mt < 2; mt++) {
                ldm4(ah[mt], st + aoff[mt][ks]);
                ldm4(al[mt], st + ST_AL + aoff[mt][ks]);
            }
#pragma unroll
            for (int ng = 0; ng < 4; ng++) {
                uint32_t bh[4], bl[4];
                ldm4(bh, st + ST_BH + boff[ng][ks]);
                ldm4(bl, st + ST_BL + boff[ng][ks]);
                // n-tiles 2*ng and 2*ng+1: frags {r0,r2} and {r1,r3}
#pragma unroll
                for (int mt = 0; mt < 2; mt++) {
                    mma16816(acc[mt][2 * ng + 0], ah[mt], bh[0], bh[2]);
                    mma16816(acc[mt][2 * ng + 1], ah[mt], bh[1], bh[3]);
                    mma16816(acc[mt][2 * ng + 0], ah[mt], bl[0], bl[2]);
                    mma16816(acc[mt][2 * ng + 1], ah[mt], bl[1], bl[3]);
                    mma16816(acc[mt][2 * ng + 0], al[mt], bh[0], bh[2]);
                    mma16816(acc[mt][2 * ng + 1], al[mt], bh[1], bh[3]);
                }
            }
        }
        __syncthreads();
        if (kc + 2 < NCHUNK) LOAD_STAGE(kc + 2, kc & 1);
    }
#undef LOAD_STAGE

    // epilogue: out[(i*128 + t)*131072 + r*256 + n]
    const int i_ch = by >> 2;
    const int t = bx >> 1;
    float* ob = out + (size_t)(i_ch * 128 + t) * 131072;
    const int rbase = (by & 3) * 128 + m0w + (lane >> 2);
    const int cbase = (bx & 1) * 128 + n0w + (lane & 3) * 2;
#pragma unroll
    for (int mt = 0; mt < 2; mt++) {
        const int r0 = rbase + mt * 16;
#pragma unroll
        for (int nt = 0; nt < 8; nt++) {
            const int c = cbase + nt * 8;
            float2 v0 = make_float2(acc[mt][nt][0], acc[mt][nt][1]);
            float2 v1 = make_float2(acc[mt][nt][2], acc[mt][nt][3]);
            __stcs((float2*)(ob + (size_t)r0 * 256 + c), v0);
            __stcs((float2*)(ob + (size_t)(r0 + 8) * 256 + c), v1);
        }
    }
}

// ---------------------------------------------------------------------------
extern "C" void kernel_launch(void* const* d_in, const int* in_sizes, int n_in,
                              void* d_out, int out_size) {
    const float* inp = (const float*)d_in[0];   // (8,64,1024)
    const float* A   = (const float*)d_in[1];   // (256,256)
    const float* Bv  = (const float*)d_in[2];   // (256,)
    float* out = (float*)d_out;

    cudaFuncSetAttribute(main_mma_kernel,
                         cudaFuncAttributeMaxDynamicSharedMemorySize, SMEM_SZ);

    init_a_kernel<<<256, 256>>>(A);
    for (int d = 1; d <= 64; d <<= 1)
        pow_double_kernel<<<dim3(4, 4, d), 256>>>(d);

    v_kernel<<<128, 256>>>(Bv);
    qt_kernel<<<256, 256>>>();
    b_limbs_kernel<<<128 * NCHUNK, 256>>>();
    s_kernel<<<dim3(512, 8), 256>>>(inp);
    for (int i = 0; i < 6; i++)
        combine_kernel<<<dim3(4, 8), 256>>>(i);
    a_limbs_kernel<<<32 * NCHUNK, 256>>>(inp);

    main_mma_kernel<<<dim3(256, 32), 256, SMEM_SZ>>>(out);
}

// round 4
// speedup vs baseline: 2.5878x; 1.2859x over previous
#include <cuda_runtime.h>
#include <cuda_fp16.h>
#include <cstdint>

// ---------------------------------------------------------------------------
// HiPPO-LegT: chunked convolution + one big GEMM.
// Main GEMM on mma.sync fp16 (2-term split: Ah*Bh + Al*Bh, fp32 acc).
//
//  out[l, r, n] = sum_{k<=l} (A^{l-k} B)[n] * f[r, k]   (r = b*64+m, R=512)
//  Chunk T=128, C=8, v_j = A^j B:
//    out(i*T+t) = sum_{k<=t} v_{t-k} f[r,iT+k] + A^{t+1} h_{i-1}
//  One GEMM: Out(4096 x 32768) = X(4096 x 384) @ Kmat(384 x 32768)
// ---------------------------------------------------------------------------

#define N_ST   256
#define T_CH   128
#define MAT    65536
#define NCHUNK 6
#define AB_BLK 16384              // bytes: 128 rows x 64 k fp16 (swizzled)
#define BB_BLK 32768              // bytes: 256 rows x 64 k fp16 (swizzled)

// main mma kernel smem: per stage [Ah 16K][Al 16K][Bh 16K]
#define ST_AL  16384
#define ST_BH  32768
#define ST_SZ  49152
#define SMEM_SZ (2 * ST_SZ)

// ---- device scratch ----
__device__ float g_Apow[129 * MAT];                    // A^1..A^128 at 1..128
__device__ float g_V[T_CH * N_ST];                     // v_j = A^j B
__device__ float g_Qp[8 * MAT];                        // (A^128)^p, p=2..7
__device__ float g_S[8 * 512 * N_ST];
__device__ float g_H[8 * 512 * N_ST];
__device__ __half g_Ah[(size_t)32 * NCHUNK * 8192];
__device__ __half g_Al[(size_t)32 * NCHUNK * 8192];
__device__ __half g_Bh[(size_t)128 * NCHUNK * 16384];

// ---------------------------------------------------------------------------
__device__ __forceinline__ uint32_t smem_u32(const void* p) {
    uint32_t a;
    asm("{ .reg .u64 t; cvta.to.shared.u64 t, %1; cvt.u32.u64 %0, t; }" : "=r"(a) : "l"(p));
    return a;
}
__device__ __forceinline__ void cp16(uint32_t s, const void* g) {
    asm volatile("cp.async.cg.shared.global [%0], [%1], 16;" :: "r"(s), "l"(g));
}
#define CP_COMMIT() asm volatile("cp.async.commit_group;" ::: "memory")
#define CP_WAIT(n)  asm volatile("cp.async.wait_group %0;" :: "n"(n) : "memory")

__device__ __forceinline__ void ldm4(uint32_t* r, uint32_t addr) {
    asm volatile("ldmatrix.sync.aligned.m8n8.x4.shared.b16 {%0,%1,%2,%3}, [%4];"
                 : "=r"(r[0]), "=r"(r[1]), "=r"(r[2]), "=r"(r[3]) : "r"(addr));
}
__device__ __forceinline__ void mma16816(float* d, const uint32_t* a,
                                         uint32_t b0, uint32_t b1) {
    asm volatile(
        "mma.sync.aligned.m16n8k16.row.col.f32.f16.f16.f32 "
        "{%0,%1,%2,%3}, {%4,%5,%6,%7}, {%8,%9}, {%0,%1,%2,%3};"
        : "+f"(d[0]), "+f"(d[1]), "+f"(d[2]), "+f"(d[3])
        : "r"(a[0]), "r"(a[1]), "r"(a[2]), "r"(a[3]), "r"(b0), "r"(b1));
}

__device__ __forceinline__ uint32_t swz(uint32_t off) { return off ^ ((off >> 3) & 0x70); }

__device__ __forceinline__ unsigned short hbits(float x) {
    __half h = __float2half_rn(x);
    return *reinterpret_cast<unsigned short*>(&h);
}
__device__ __forceinline__ void split2h(float x, unsigned short& h, unsigned short& l) {
    __half hh = __float2half_rn(x);
    h = *reinterpret_cast<unsigned short*>(&hh);
    l = hbits(x - __half2float(hh));
}

// ---------------------------------------------------------------------------
// prologue kernels (fp32 SIMT)
// ---------------------------------------------------------------------------
__global__ void init_a_kernel(const float* __restrict__ A) {
    int idx = blockIdx.x * blockDim.x + threadIdx.x;
    if (idx < MAT) g_Apow[MAT + idx] = A[idx];
}

__device__ __forceinline__ void gemm64_body(const float* __restrict__ Am,
                                            const float* __restrict__ Bm,
                                            float* __restrict__ Cm,
                                            const float* __restrict__ bias) {
    __shared__ float As[16][64];
    __shared__ float Bs[16][64];
    const int brow = blockIdx.y * 64;
    const int bcol = blockIdx.x * 64;
    const int tid = threadIdx.x;
    const int tr = tid >> 4, tc = tid & 15;
    const int alr = tid >> 2, alc = (tid & 3) * 4;
    const int blr = tid >> 4, blc = (tid & 15) * 4;
    float acc[4][4] = {};
    for (int k0 = 0; k0 < 256; k0 += 16) {
        float4 a4 = *(const float4*)&Am[(brow + alr) * 256 + k0 + alc];
        As[alc + 0][alr] = a4.x; As[alc + 1][alr] = a4.y;
        As[alc + 2][alr] = a4.z; As[alc + 3][alr] = a4.w;
        float4 b4 = *(const float4*)&Bm[(k0 + blr) * 256 + bcol + blc];
        *(float4*)&Bs[blr][blc] = b4;
        __syncthreads();
#pragma unroll
        for (int k = 0; k < 16; k++) {
            float av[4], bv[4];
            *(float4*)&av[0] = *(const float4*)&As[k][tr * 4];
            *(float4*)&bv[0] = *(const float4*)&Bs[k][tc * 4];
#pragma unroll
            for (int ii = 0; ii < 4; ii++)
#pragma unroll
                for (int jj = 0; jj < 4; jj++)
                    acc[ii][jj] += av[ii] * bv[jj];
        }
        __syncthreads();
    }
#pragma unroll
    for (int ii = 0; ii < 4; ii++) {
        int rr = brow + tr * 4 + ii;
        int cc = bcol + tc * 4;
        float4 v;
        v.x = acc[ii][0]; v.y = acc[ii][1]; v.z = acc[ii][2]; v.w = acc[ii][3];
        if (bias) {
            float4 b = *(const float4*)&bias[rr * 256 + cc];
            v.x += b.x; v.y += b.y; v.z += b.z; v.w += b.w;
        }
        *(float4*)&Cm[rr * 256 + cc] = v;
    }
}

__global__ void pow_double_kernel(int d) {
    int j = blockIdx.z + 1;
    gemm64_body(g_Apow + (size_t)d * MAT, g_Apow + (size_t)j * MAT,
                g_Apow + (size_t)(d + j) * MAT, nullptr);
}

// Qp chain: Qp[p] = (A^128)^p
__global__ void qp2_kernel() {
    gemm64_body(g_Apow + (size_t)128 * MAT, g_Apow + (size_t)128 * MAT,
                g_Qp + (size_t)2 * MAT, nullptr);
}
__global__ void qp34_kernel() {
    if (blockIdx.z == 0)
        gemm64_body(g_Qp + (size_t)2 * MAT, g_Apow + (size_t)128 * MAT,
                    g_Qp + (size_t)3 * MAT, nullptr);
    else
        gemm64_body(g_Qp + (size_t)2 * MAT, g_Qp + (size_t)2 * MAT,
                    g_Qp + (size_t)4 * MAT, nullptr);
}
__global__ void qp567_kernel() {
    const float* rhs = (blockIdx.z == 0) ? g_Apow + (size_t)128 * MAT
                                         : g_Qp + (size_t)(blockIdx.z + 1) * MAT;
    gemm64_body(g_Qp + (size_t)4 * MAT, rhs,
                g_Qp + (size_t)(5 + blockIdx.z) * MAT, nullptr);
}

__global__ void v_kernel(const float* __restrict__ Bv) {
    __shared__ float bs[256];
    int j = blockIdx.x, n = threadIdx.x;
    bs[n] = Bv[n];
    __syncthreads();
    if (j == 0) { g_V[n] = bs[n]; return; }
    const float* Am = g_Apow + (size_t)j * MAT;
    float s = 0.f;
#pragma unroll 8
    for (int m = 0; m < 256; m++) s += Am[n * 256 + m] * bs[m];
    g_V[j * 256 + n] = s;
}

__global__ void s_kernel(const float* __restrict__ inp) {
    __shared__ float fs[128];
    int r = blockIdx.x, i = blockIdx.y, n = threadIdx.x;
    if (n < 128) fs[n] = inp[r * 1024 + i * T_CH + n];
    __syncthreads();
    float s = 0.f;
#pragma unroll 4
    for (int k = 0; k < 128; k++)
        s += g_V[(127 - k) * 256 + n] * fs[k];
    g_S[(i * 512 + r) * 256 + n] = s;
    if (i == 0) g_H[r * 256 + n] = s;
}

// H[i] = S[i] + sum_{j<i} S[j] * Qp[i-j]^T     (one parallel launch, i=1..7)
__global__ void combine_all_kernel() {
    __shared__ float As[16][64];
    __shared__ float Bs[16][64];
    const int i = blockIdx.z + 1;
    const int brow = blockIdx.y * 64;
    const int bcol = blockIdx.x * 64;
    const int tid = threadIdx.x;
    const int tr = tid >> 4, tc = tid & 15;
    const int alr = tid >> 2, alc = (tid & 3) * 4;
    const int bc = tid >> 2, bk = (tid & 3) * 4;
    float acc[4][4] = {};
    for (int j = 0; j < i; j++) {
        const int p = i - j;
        const float* Qp = (p == 1) ? g_Apow + (size_t)128 * MAT
                                   : g_Qp + (size_t)p * MAT;
        const float* Sj = g_S + (size_t)j * (512 * 256);
        for (int k0 = 0; k0 < 256; k0 += 16) {
            float4 a4 = *(const float4*)&Sj[(brow + alr) * 256 + k0 + alc];
            As[alc + 0][alr] = a4.x; As[alc + 1][alr] = a4.y;
            As[alc + 2][alr] = a4.z; As[alc + 3][alr] = a4.w;
            float4 q4 = *(const float4*)&Qp[(size_t)(bcol + bc) * 256 + k0 + bk];
            Bs[bk + 0][bc] = q4.x; Bs[bk + 1][bc] = q4.y;
            Bs[bk + 2][bc] = q4.z; Bs[bk + 3][bc] = q4.w;
            __syncthreads();
#pragma unroll
            for (int k = 0; k < 16; k++) {
                float av[4], bv[4];
                *(float4*)&av[0] = *(const float4*)&As[k][tr * 4];
                *(float4*)&bv[0] = *(const float4*)&Bs[k][tc * 4];
#pragma unroll
                for (int ii = 0; ii < 4; ii++)
#pragma unroll
                    for (int jj = 0; jj < 4; jj++)
                        acc[ii][jj] += av[ii] * bv[jj];
            }
            __syncthreads();
        }
    }
    float* Hout = g_H + (size_t)i * (512 * 256);
    const float* Si = g_S + (size_t)i * (512 * 256);
#pragma unroll
    for (int ii = 0; ii < 4; ii++) {
        int rr = brow + tr * 4 + ii;
        int cc = bcol + tc * 4;
        float4 b = *(const float4*)&Si[rr * 256 + cc];
        float4 v;
        v.x = acc[ii][0] + b.x; v.y = acc[ii][1] + b.y;
        v.z = acc[ii][2] + b.z; v.w = acc[ii][3] + b.w;
        *(float4*)&Hout[rr * 256 + cc] = v;
    }
}

// ---------------------------------------------------------------------------
// limb-split packers (fp16), SW128-swizzled, exact smem image.
// B block (t, kc): 256 rows(n) x 64 k fp16;  value = Kmat[kc*64+kk][t*256+n]
// A block (rt, kc): 128 rows x 64 k fp16;    value = X[rt*128+row][kc*64+kk]
// ---------------------------------------------------------------------------
__global__ void b_limbs_kernel() {
    const int blk = blockIdx.x;            // t*6 + kc
    const int t = blk / NCHUNK, kc = blk % NCHUNK;
    const int tid = threadIdx.x;
    const int kk0 = (tid & 15) * 4;
    char* dh = (char*)g_Bh + (size_t)blk * BB_BLK;
    for (int it = 0; it < 16; it++) {
        int n = it * 16 + (tid >> 4);
        float v[4];
        if (kc < 2) {
            int k0 = kc * 64 + kk0;
#pragma unroll
            for (int q = 0; q < 4; q++) {
                int k = k0 + q;
                v[q] = (k <= t) ? g_V[(t - k) * 256 + n] : 0.f;
            }
        } else {
            int m0 = kc * 64 + kk0 - 128;
            float4 a4 = *(const float4*)&g_Apow[(size_t)(t + 1) * MAT + n * 256 + m0];
            v[0] = a4.x; v[1] = a4.y; v[2] = a4.z; v[3] = a4.w;
        }
        uint2 ph;
        ph.x = (uint32_t)hbits(v[0]) | ((uint32_t)hbits(v[1]) << 16);
        ph.y = (uint32_t)hbits(v[2]) | ((uint32_t)hbits(v[3]) << 16);
        uint32_t off = swz((uint32_t)(n * 128 + kk0 * 2));
        *(uint2*)(dh + off) = ph;
    }
}

__global__ void a_limbs_kernel(const float* __restrict__ inp) {
    const int blk = blockIdx.x;            // rt*6 + kc
    const int rt = blk / NCHUNK, kc = blk % NCHUNK;
    const int i = rt >> 2;
    const int tid = threadIdx.x;
    const int kk0 = (tid & 15) * 4;
    char* dh = (char*)g_Ah + (size_t)blk * AB_BLK;
    char* dl = (char*)g_Al + (size_t)blk * AB_BLK;
    for (int it = 0; it < 8; it++) {
        int row = it * 16 + (tid >> 4);
        int r = (rt & 3) * 128 + row;
        float v[4];
        if (kc < 2) {
            float4 f4 = *(const float4*)&inp[r * 1024 + i * 128 + kc * 64 + kk0];
            v[0] = f4.x; v[1] = f4.y; v[2] = f4.z; v[3] = f4.w;
        } else if (i == 0) {
            v[0] = v[1] = v[2] = v[3] = 0.f;
        } else {
            float4 f4 = *(const float4*)&g_H[(size_t)((i - 1) * 512 + r) * 256 +
                                             (kc - 2) * 64 + kk0];
            v[0] = f4.x; v[1] = f4.y; v[2] = f4.z; v[3] = f4.w;
        }
        unsigned short h[4], l[4];
#pragma unroll
        for (int q = 0; q < 4; q++) split2h(v[q], h[q], l[q]);
        uint2 ph, pl;
        ph.x = (uint32_t)h[0] | ((uint32_t)h[1] << 16);
        ph.y = (uint32_t)h[2] | ((uint32_t)h[3] << 16);
        pl.x = (uint32_t)l[0] | ((uint32_t)l[1] << 16);
        pl.y = (uint32_t)l[2] | ((uint32_t)l[3] << 16);
        uint32_t off = swz((uint32_t)(row * 128 + kk0 * 2));
        *(uint2*)(dh + off) = ph;
        *(uint2*)(dl + off) = pl;
    }
}

// ---------------------------------------------------------------------------
// Main GEMM: mma.sync fp16 2-term. CTA = 128x128 out tile, chunks of K=64,
// cp.async double-buffered, causal zero-chunk skipped. 8 warps, 32x64 each.
// grid (256 col tiles, 32 row tiles).
// ---------------------------------------------------------------------------
__global__ __launch_bounds__(256, 2) void main_mma_kernel(float* __restrict__ out) {
    extern __shared__ char smem[];
    const uint32_t sb = smem_u32(smem);
    const int tid = threadIdx.x;
    const int wid = tid >> 5;
    const int lane = tid & 31;
    const int bx = blockIdx.x;          // t = bx>>1, n-half = bx&1
    const int by = blockIdx.y;          // row tile
    const int t = bx >> 1;

    const int m0w = (wid & 3) * 32;
    const int n0w = (wid >> 2) * 64;

    // chunk list: skip kc=1 when t<64 (all-zero causal block)
    int clist[6] = {0, 1, 2, 3, 4, 5};
    int nch = 6;
    if (t < 64) { clist[1] = 2; clist[2] = 3; clist[3] = 4; clist[4] = 5; nch = 5; }

    const char* Asrc_h = (const char*)g_Ah + (size_t)by * NCHUNK * AB_BLK;
    const char* Asrc_l = (const char*)g_Al + (size_t)by * NCHUNK * AB_BLK;
    const char* Bsrc   = (const char*)g_Bh + (size_t)t * NCHUNK * BB_BLK
                         + (size_t)(bx & 1) * 16384;

    const uint32_t cpo = (uint32_t)tid * 16;

    uint32_t aoff[2][4];
    uint32_t boff[4][4];
    {
        const uint32_t arow = (uint32_t)(m0w + (lane & 15)) * 128;
        const uint32_t khalf = (uint32_t)(lane >> 4) * 16;
#pragma unroll
        for (int mt = 0; mt < 2; mt++)
#pragma unroll
            for (int ks = 0; ks < 4; ks++)
                aoff[mt][ks] = swz(arow + (uint32_t)mt * 16 * 128 + khalf + ks * 32);
        const uint32_t brow = (uint32_t)(n0w + (lane & 15)) * 128;
#pragma unroll
        for (int ng = 0; ng < 4; ng++)
#pragma unroll
            for (int ks = 0; ks < 4; ks++)
                boff[ng][ks] = swz(brow + (uint32_t)ng * 16 * 128 + khalf + ks * 32);
    }

    float acc[2][8][4];
#pragma unroll
    for (int mt = 0; mt < 2; mt++)
#pragma unroll
        for (int nt = 0; nt < 8; nt++)
#pragma unroll
            for (int q = 0; q < 4; q++) acc[mt][nt][q] = 0.f;

#define LOAD_STAGE(kc, st)                                                      \
    do {                                                                        \
        uint32_t s0 = sb + (st) * ST_SZ + cpo;                                  \
        const char* ga = Asrc_h + (size_t)(kc) * AB_BLK + cpo;                  \
        const char* gb = Asrc_l + (size_t)(kc) * AB_BLK + cpo;                  \
        const char* gc = Bsrc + (size_t)(kc) * BB_BLK + cpo;                    \
        _Pragma("unroll")                                                       \
        for (int q = 0; q < 4; q++) {                                           \
            cp16(s0 + q * 4096,         ga + q * 4096);                         \
            cp16(s0 + ST_AL + q * 4096, gb + q * 4096);                         \
            cp16(s0 + ST_BH + q * 4096, gc + q * 4096);                         \
        }                                                                       \
        CP_COMMIT();                                                            \
    } while (0)

    LOAD_STAGE(clist[0], 0);
    LOAD_STAGE(clist[1], 1);

    for (int j = 0; j < nch; j++) {
        if (j + 2 < nch) CP_WAIT(1); else CP_WAIT(0);
        __syncthreads();
        const uint32_t st = sb + (uint32_t)(j & 1) * ST_SZ;
#pragma unroll
        for (int ks = 0; ks < 4; ks++) {
            uint32_t ah[2][4], al[2][4];
#pragma unroll
            for (int mt = 0; mt < 2; mt++) {
                ldm4(ah[mt], st + aoff[mt][ks]);
                ldm4(al[mt], st + ST_AL + aoff[mt][ks]);
            }
#pragma unroll
            for (int ng = 0; ng < 4; ng++) {
                uint32_t bh[4];
                ldm4(bh, st + ST_BH + boff[ng][ks]);
#pragma unroll
                for (int mt = 0; mt < 2; mt++) {
                    mma16816(acc[mt][2 * ng + 0], ah[mt], bh[0], bh[2]);
                    mma16816(acc[mt][2 * ng + 1], ah[mt], bh[1], bh[3]);
                    mma16816(acc[mt][2 * ng + 0], al[mt], bh[0], bh[2]);
                    mma16816(acc[mt][2 * ng + 1], al[mt], bh[1], bh[3]);
                }
            }
        }
        __syncthreads();
        if (j + 2 < nch) LOAD_STAGE(clist[j + 2], j & 1);
    }
#undef LOAD_STAGE

    // epilogue: out[(i*128 + t)*131072 + r*256 + n]
    const int i_ch = by >> 2;
    float* ob = out + (size_t)(i_ch * 128 + t) * 131072;
    const int rbase = (by & 3) * 128 + m0w + (lane >> 2);
    const int cbase = (bx & 1) * 128 + n0w + (lane & 3) * 2;
#pragma unroll
    for (int mt = 0; mt < 2; mt++) {
        const int r0 = rbase + mt * 16;
#pragma unroll
        for (int nt = 0; nt < 8; nt++) {
            const int c = cbase + nt * 8;
            float2 v0 = make_float2(acc[mt][nt][0], acc[mt][nt][1]);
            float2 v1 = make_float2(acc[mt][nt][2], acc[mt][nt][3]);
            __stcs((float2*)(ob + (size_t)r0 * 256 + c), v0);
            __stcs((float2*)(ob + (size_t)(r0 + 8) * 256 + c), v1);
        }
    }
}

// ---------------------------------------------------------------------------
extern "C" void kernel_launch(void* const* d_in, const int* in_sizes, int n_in,
                              void* d_out, int out_size) {
    const float* inp = (const float*)d_in[0];   // (8,64,1024)
    const float* A   = (const float*)d_in[1];   // (256,256)
    const float* Bv  = (const float*)d_in[2];   // (256,)
    float* out = (float*)d_out;

    cudaFuncSetAttribute(main_mma_kernel,
                         cudaFuncAttributeMaxDynamicSharedMemorySize, SMEM_SZ);

    init_a_kernel<<<256, 256>>>(A);
    for (int d = 1; d <= 64; d <<= 1)
        pow_double_kernel<<<dim3(4, 4, d), 256>>>(d);

    v_kernel<<<128, 256>>>(Bv);
    qp2_kernel<<<dim3(4, 4), 256>>>();
    qp34_kernel<<<dim3(4, 4, 2), 256>>>();
    qp567_kernel<<<dim3(4, 4, 3), 256>>>();
    b_limbs_kernel<<<128 * NCHUNK, 256>>>();
    s_kernel<<<dim3(512, 8), 256>>>(inp);
    combine_all_kernel<<<dim3(4, 8, 7), 256>>>();
    a_limbs_kernel<<<32 * NCHUNK, 256>>>(inp);

    main_mma_kernel<<<dim3(256, 32), 256, SMEM_SZ>>>(out);
}